// round 15
// baseline (speedup 1.0000x reference)
#include <cuda_runtime.h>
#include <cuda_bf16.h>
#include <math.h>
#include <stdint.h>

#define HW      65536
#define BATCH   4

// ---------------- scratch (device globals; no allocation allowed) ----------
// pair channel pc <-> fp channels (c0, c1): c0 = (pc>>3)*16 + (pc&7), c1 = c0+8
__device__ unsigned g_out1p[(size_t)BATCH * 32  * HW];  //  34 MB
__device__ unsigned g_catp [(size_t)BATCH * 128 * HW];  // 134 MB (k2 = dir*32+pc)
__device__ unsigned g_out2p[(size_t)BATCH * 32  * HW];  //  34 MB
__device__ unsigned g_a1p  [(size_t)BATCH * 16  * HW];  //  17 MB
__device__ unsigned g_a2p  [(size_t)BATCH * 16  * HW];  //  17 MB

// ---------------- helpers ---------------------------------------------------
__device__ __forceinline__ unsigned f2tf(float f) {
    unsigned u;
    asm("cvt.rna.tf32.f32 %0, %1;" : "=r"(u) : "f"(f));
    return u;
}
__device__ __forceinline__ unsigned packbf(float hi, float lo) {
    unsigned r;
    asm("cvt.rn.bf16x2.f32 %0, %1, %2;" : "=r"(r) : "f"(hi), "f"(lo));
    return r;
}
__device__ __forceinline__ float2 unpackbf(unsigned u) {
    __nv_bfloat162 h = *reinterpret_cast<__nv_bfloat162*>(&u);
    return __bfloat1622float2(h);
}
__device__ __forceinline__ void cpasync16(void* dst, const void* src) {
    unsigned d = (unsigned)__cvta_generic_to_shared(dst);
    asm volatile("cp.async.cg.shared.global [%0], [%1], 16;" :: "r"(d), "l"(src));
}

#define MMA_TF32(c, a, b0, b1)                                              \
    asm volatile("mma.sync.aligned.m16n8k8.row.col.f32.tf32.tf32.f32 "      \
        "{%0,%1,%2,%3}, {%4,%5,%6,%7}, {%8,%9}, {%0,%1,%2,%3};"             \
        : "+f"((c)[0]), "+f"((c)[1]), "+f"((c)[2]), "+f"((c)[3])            \
        : "r"((a)[0]), "r"((a)[1]), "r"((a)[2]), "r"((a)[3]),               \
          "r"(b0), "r"(b1))

#define MMA_BF16(c, a, b0, b1)                                              \
    asm volatile("mma.sync.aligned.m16n8k16.row.col.f32.bf16.bf16.f32 "     \
        "{%0,%1,%2,%3}, {%4,%5,%6,%7}, {%8,%9}, {%0,%1,%2,%3};"             \
        : "+f"((c)[0]), "+f"((c)[1]), "+f"((c)[2]), "+f"((c)[3])            \
        : "r"((a)[0]), "r"((a)[1]), "r"((a)[2]), "r"((a)[3]),               \
          "r"(b0), "r"(b1))

// ---------------------------------------------------------------------------
// TF32 GEMM stage 1 (K=64): out1p(packed) = w_in @ x.  grid (256,1,1)/batch.
// ---------------------------------------------------------------------------
#define G64_XS   (64 * 264)
#define G64_WS   (64 * 68)
#define G64_SMEM ((G64_XS + G64_WS) * 4)

__global__ __launch_bounds__(256, 2)
void k_gemm_tc64(const float* __restrict__ Wt, const float* __restrict__ X,
                 unsigned* __restrict__ Yp)
{
    extern __shared__ float dsm64[];
    float*    xs = dsm64;
    unsigned* ws = (unsigned*)(dsm64 + G64_XS);

    const int tid  = threadIdx.x;
    const int warp = tid >> 5;
    const int lane = tid & 31;
    const int n0   = blockIdx.x * 256;
    const float* Xb = X;
    unsigned*    Yb = Yp;

    const int mw = (warp & 1) * 32;
    const int nw = (warp >> 1) * 64;
    const int qt = lane >> 2;
    const int rt = lane & 3;

#pragma unroll
    for (int j = 0; j < 16; j++) {
        int idx = tid + j * 256;
        int k   = idx >> 6;
        int c4  = (idx & 63) * 4;
        cpasync16(&xs[k * 264 + c4], Xb + (size_t)k * HW + n0 + c4);
    }
    asm volatile("cp.async.commit_group;");

#pragma unroll
    for (int i = 0; i < 16; i++) {
        int e = tid + i * 256;
        int m = e >> 6, k = e & 63;
        ws[m * 68 + k] = f2tf(Wt[m * 64 + k]);
    }
    asm volatile("cp.async.wait_group 0;");
    __syncthreads();

    float acc[2][8][4];
#pragma unroll
    for (int i = 0; i < 2; i++)
#pragma unroll
        for (int j = 0; j < 8; j++)
#pragma unroll
            for (int v = 0; v < 4; v++) acc[i][j][v] = 0.f;

#pragma unroll
    for (int kk = 0; kk < 8; kk++) {
        const int kb = kk * 8;
        unsigned a[2][4];
#pragma unroll
        for (int mt = 0; mt < 2; mt++) {
            int mr = mw + mt * 16 + qt;
            a[mt][0] = ws[mr * 68 + kb + rt];
            a[mt][1] = ws[(mr + 8) * 68 + kb + rt];
            a[mt][2] = ws[mr * 68 + kb + rt + 4];
            a[mt][3] = ws[(mr + 8) * 68 + kb + rt + 4];
        }
#pragma unroll
        for (int nt = 0; nt < 8; nt++) {
            int col = nw + nt * 8 + qt;
            unsigned b0 = f2tf(xs[(kb + rt) * 264 + col]);
            unsigned b1 = f2tf(xs[(kb + rt + 4) * 264 + col]);
            MMA_TF32(acc[0][nt], a[0], b0, b1);
            MMA_TF32(acc[1][nt], a[1], b0, b1);
        }
    }

#pragma unroll
    for (int mt = 0; mt < 2; mt++) {
        int pc = ((mw >> 4) + mt) * 8 + qt;
#pragma unroll
        for (int nt = 0; nt < 8; nt++) {
            int col = n0 + nw + nt * 8 + rt * 2;
            uint2 u;
            u.x = packbf(acc[mt][nt][2], acc[mt][nt][0]);
            u.y = packbf(acc[mt][nt][3], acc[mt][nt][1]);
            *(uint2*)&Yb[(size_t)pc * HW + col] = u;
        }
    }
}

// ---------------------------------------------------------------------------
// 4-direction IRNN scans, per-batch launch: grid 128 = 4 dirs x 32 pc.
// ---------------------------------------------------------------------------
__global__ __launch_bounds__(256)
void k_scans4(const unsigned* __restrict__ srcp, unsigned* __restrict__ catp,
              const float* __restrict__ w_up, const float* __restrict__ b_up,
              const float* __restrict__ w_rt, const float* __restrict__ b_rt,
              const float* __restrict__ w_dn, const float* __restrict__ b_dn,
              const float* __restrict__ w_lt, const float* __restrict__ b_lt)
{
    const int dir = blockIdx.x >> 5;
    const int pc  = blockIdx.x & 31;
    const int tid = threadIdx.x;
    const int c0  = ((pc >> 3) * 16) + (pc & 7);
    const int c1  = c0 + 8;

    const float *wv, *bv;
    int k2off; bool vert, fwd;
    if (dir == 0)      { wv = w_dn; bv = b_dn; k2off = 64; vert = true;  fwd = true;  }
    else if (dir == 1) { wv = w_up; bv = b_up; k2off = 0;  vert = true;  fwd = false; }
    else if (dir == 2) { wv = w_rt; bv = b_rt; k2off = 32; vert = false; fwd = true;  }
    else               { wv = w_lt; bv = b_lt; k2off = 96; vert = false; fwd = false; }

    const float W0 = wv[c0], W1 = wv[c1], B0 = bv[c0], B1 = bv[c1];

    int off  = vert ? tid : tid * 256;
    int step = vert ? 256 : 1;
    if (!fwd) { off += step * 255; step = -step; }

    const unsigned* sp = srcp + ((size_t)pc << 16) + off;
    unsigned*       dp = catp + (((size_t)k2off + pc) << 16) + off;

    float h0 = 0.f, h1 = 0.f;
    unsigned v = *sp;
    sp += step;
#pragma unroll 8
    for (int i = 0; i < 256; i++) {
        unsigned vn = 0;
        if (i < 255) vn = *sp;
        sp += step;
        float2 f = unpackbf(v);
        h0 = fmaxf(fmaf(W0, h0, f.x + B0), 0.f);
        h1 = fmaxf(fmaf(W1, h1, f.y + B1), 0.f);
        *dp = packbf(h1, h0);
        dp += step;
        v = vn;
    }
}

// ---------------------------------------------------------------------------
// BF16 GEMM stage 3: out2p = relu(wD2 @ cat), K=256 (128 pairs).
// Full A resident in smem (stride 132), 3-stage cp.async ring for B
// (stride 264, conflict-free). grid (256,1,1)/batch.
// ---------------------------------------------------------------------------
#define G256_WS   (64 * 132)
#define G256_XSLOT (16 * 264)
#define G256_SMEM ((G256_WS + 3 * G256_XSLOT) * 4)

__global__ __launch_bounds__(256)
void k_gemm256_bf16(const float* __restrict__ Wt, const unsigned* __restrict__ Xp,
                    unsigned* __restrict__ Yp)
{
    extern __shared__ unsigned dsm[];
    unsigned* wsf = dsm;
    unsigned* xsp = dsm + G256_WS;

    const int tid  = threadIdx.x;
    const int warp = tid >> 5;
    const int lane = tid & 31;
    const int n0   = blockIdx.x * 256;
    const unsigned* Xb = Xp;
    unsigned*       Yb = Yp;

    const int nw = warp * 32;
    const int qt = lane >> 2;
    const int rt = lane & 3;

#pragma unroll
    for (int c = 0; c < 2; c++) {
#pragma unroll
        for (int j = 0; j < 4; j++) {
            int idx = tid + j * 256, row = idx >> 6, col4 = (idx & 63) * 4;
            cpasync16(&xsp[c * G256_XSLOT + row * 264 + col4],
                      Xb + (size_t)(c * 16 + row) * HW + n0 + col4);
        }
        asm volatile("cp.async.commit_group;");
    }

#pragma unroll
    for (int i = 0; i < 32; i++) {
        int e = tid + i * 256;
        int m = e >> 7, l2 = e & 127;
        int d2 = l2 >> 5, pcd = l2 & 31;
        int cc = d2 * 64 + ((pcd >> 3) * 16) + (pcd & 7);
        wsf[m * 132 + l2] = packbf(Wt[m * 256 + cc + 8], Wt[m * 256 + cc]);
    }

    float acc[4][4][4];
#pragma unroll
    for (int i = 0; i < 4; i++)
#pragma unroll
        for (int j = 0; j < 4; j++)
#pragma unroll
            for (int v = 0; v < 4; v++) acc[i][j][v] = 0.f;

    for (int kt = 0; kt < 8; kt++) {
        __syncthreads();
        if (kt + 2 < 8) {
            int sl = (kt + 2) % 3;
#pragma unroll
            for (int j = 0; j < 4; j++) {
                int idx = tid + j * 256, row = idx >> 6, col4 = (idx & 63) * 4;
                cpasync16(&xsp[sl * G256_XSLOT + row * 264 + col4],
                          Xb + (size_t)((kt + 2) * 16 + row) * HW + n0 + col4);
            }
            asm volatile("cp.async.commit_group;");
        }
        if (kt < 6)      asm volatile("cp.async.wait_group 2;");
        else if (kt == 6) asm volatile("cp.async.wait_group 1;");
        else              asm volatile("cp.async.wait_group 0;");
        __syncthreads();

        const unsigned* xc = xsp + (kt % 3) * G256_XSLOT;
        const int kg = kt * 16;
#pragma unroll
        for (int s = 0; s < 2; s++) {
            const int kb = s * 8;
            unsigned a[4][4];
#pragma unroll
            for (int mt = 0; mt < 4; mt++) {
                int m = mt * 16 + qt;
                int k2 = kg + kb + rt;
                a[mt][0] = wsf[m * 132 + k2];
                a[mt][1] = wsf[(m + 8) * 132 + k2];
                a[mt][2] = wsf[m * 132 + k2 + 4];
                a[mt][3] = wsf[(m + 8) * 132 + k2 + 4];
            }
#pragma unroll
            for (int nt = 0; nt < 4; nt++) {
                int col = nw + nt * 8 + qt;
                unsigned b0 = xc[(kb + rt) * 264 + col];
                unsigned b1 = xc[(kb + rt + 4) * 264 + col];
#pragma unroll
                for (int mt = 0; mt < 4; mt++)
                    MMA_BF16(acc[mt][nt], a[mt], b0, b1);
            }
        }
    }

#pragma unroll
    for (int mt = 0; mt < 4; mt++) {
        int pc = mt * 8 + qt;
#pragma unroll
        for (int nt = 0; nt < 4; nt++) {
            int col = n0 + nw + nt * 8 + rt * 2;
            uint2 u;
            u.x = packbf(fmaxf(acc[mt][nt][2], 0.f), fmaxf(acc[mt][nt][0], 0.f));
            u.y = packbf(fmaxf(acc[mt][nt][3], 0.f), fmaxf(acc[mt][nt][1], 0.f));
            *(uint2*)&Yb[(size_t)pc * HW + col] = u;
        }
    }
}

// ---------------------------------------------------------------------------
// BF16 3x3 conv on packed pairs (R11 version). grid (128,1,1)/batch.
// ---------------------------------------------------------------------------
#define CONV_XSLOT (4 * 8 * 264)
#define CONV_WSLOT (9 * 8 * 40)
#define CONV_SMEM  ((2 * CONV_XSLOT + 2 * CONV_WSLOT) * 4)

template<int NPAIR>
__global__ __launch_bounds__(256, 2)
void k_conv3p(const unsigned* __restrict__ inp, const float* __restrict__ wt,
              const float* __restrict__ bias, unsigned* __restrict__ outp)
{
    constexpr int CI  = NPAIR * 2;
    constexpr int NCH = NPAIR / 8;

    extern __shared__ unsigned dsm[];
    unsigned* xsb = dsm;
    unsigned* wsb = dsm + 2 * CONV_XSLOT;

    const int h0    = blockIdx.x * 2;
    const int tid   = threadIdx.x;
    const int warp  = tid >> 5;
    const int lane  = tid & 31;
    const int rw    = warp >> 2;
    const int strip = (warp & 3) * 64;
    const int qt    = lane >> 2;
    const int rt    = lane & 3;

    const unsigned* inb = inp;

    if (tid < 128) {
        int buf = tid >> 6, rem = tid & 63;
        int side = rem >> 5, rr = (rem >> 3) & 3, i2 = rem & 7;
        xsb[buf * CONV_XSLOT + (rr * 8 + i2) * 264 + (side ? 260 : 3)] = 0u;
    }

    float acc[2][8][4];
#pragma unroll
    for (int i = 0; i < 2; i++)
#pragma unroll
        for (int j = 0; j < 8; j++)
#pragma unroll
            for (int v = 0; v < 4; v++) acc[i][j][v] = 0.f;

#define STAGE_X(CH, XD)                                                       \
    {                                                                         \
        unsigned* xd = (XD);                                                  \
        _Pragma("unroll")                                                     \
        for (int j = 0; j < 8; j++) {                                         \
            int e  = tid + j * 256;                                           \
            int i2 = e >> 8;                                                  \
            int r  = (e >> 6) & 3;                                            \
            int bk = e & 63;                                                  \
            int hh = h0 + r - 1;                                              \
            unsigned* dst = &xd[(r * 8 + i2) * 264 + 4 + bk * 4];             \
            if ((unsigned)hh < 256u)                                          \
                cpasync16(dst, inb + (size_t)((CH) * 8 + i2) * HW + hh * 256 + bk * 4); \
            else                                                              \
                *(uint4*)dst = make_uint4(0, 0, 0, 0);                        \
        }                                                                     \
        asm volatile("cp.async.commit_group;");                               \
    }

#define STAGE_W(CH, WD)                                                       \
    {                                                                         \
        unsigned* wd = (WD);                                                  \
        for (int e = tid; e < 9 * 8 * 32; e += 256) {                         \
            int tap = e >> 8;                                                 \
            int i2  = (e >> 5) & 7;                                           \
            int o   = e & 31;                                                 \
            int pg  = (CH) * 8 + i2;                                          \
            int cc  = ((pg >> 3) * 16) + (pg & 7);                            \
            const float* p = wt + ((size_t)o * CI + cc) * 9 + tap;            \
            wd[(tap * 8 + i2) * 40 + o] = packbf(p[72], p[0]);                \
        }                                                                     \
    }

#define LOADFRAG(TAP, S)                                                      \
    {                                                                         \
        const int r_ = (TAP) / 3, c_ = (TAP) % 3;                             \
        const int ri_ = rw + r_;                                              \
        _Pragma("unroll")                                                     \
        for (int mt = 0; mt < 2; mt++) {                                      \
            int o = mt * 16 + qt;                                             \
            af[S][mt][0] = wc[((TAP) * 8 + rt) * 40 + o];                     \
            af[S][mt][1] = wc[((TAP) * 8 + rt) * 40 + o + 8];                 \
            af[S][mt][2] = wc[((TAP) * 8 + rt + 4) * 40 + o];                 \
            af[S][mt][3] = wc[((TAP) * 8 + rt + 4) * 40 + o + 8];             \
        }                                                                     \
        _Pragma("unroll")                                                     \
        for (int nt = 0; nt < 8; nt++) {                                      \
            int col = strip + nt * 8 + qt + c_ + 3;                           \
            bf[S][nt][0] = xc[(ri_ * 8 + rt) * 264 + col];                    \
            bf[S][nt][1] = xc[(ri_ * 8 + rt + 4) * 264 + col];                \
        }                                                                     \
    }

    STAGE_X(0, xsb + 0);
    STAGE_W(0, wsb + 0);

    for (int ch = 0; ch < NCH; ch++) {
        const int cur = ch & 1, nxt = cur ^ 1;
        __syncthreads();
        if (ch + 1 < NCH) {
            STAGE_X(ch + 1, xsb + nxt * CONV_XSLOT);
            STAGE_W(ch + 1, wsb + nxt * CONV_WSLOT);
            asm volatile("cp.async.wait_group 1;");
        } else {
            asm volatile("cp.async.wait_group 0;");
        }
        __syncthreads();

        const unsigned* xc = xsb + cur * CONV_XSLOT;
        const unsigned* wc = wsb + cur * CONV_WSLOT;

        unsigned af[2][2][4];
        unsigned bf[2][8][2];
        LOADFRAG(0, 0);
#pragma unroll
        for (int tap = 0; tap < 9; tap++) {
            const int cb = tap & 1;
            if (tap < 8) LOADFRAG(tap + 1, cb ^ 1);
#pragma unroll
            for (int nt = 0; nt < 8; nt++) {
                MMA_BF16(acc[0][nt], af[cb][0], bf[cb][nt][0], bf[cb][nt][1]);
                MMA_BF16(acc[1][nt], af[cb][1], bf[cb][nt][0], bf[cb][nt][1]);
            }
        }
    }
#undef STAGE_X
#undef STAGE_W
#undef LOADFRAG

    const int orow = (h0 + rw) * 256;
#pragma unroll
    for (int mt = 0; mt < 2; mt++) {
        int o   = mt * 16 + qt;
        int pc  = mt * 8 + qt;
        float bv0 = bias[o];
        float bv1 = bias[o + 8];
#pragma unroll
        for (int nt = 0; nt < 8; nt++) {
            int col = strip + nt * 8 + rt * 2;
            uint2 u;
            u.x = packbf(fmaxf(acc[mt][nt][2] + bv1, 0.f),
                         fmaxf(acc[mt][nt][0] + bv0, 0.f));
            u.y = packbf(fmaxf(acc[mt][nt][3] + bv1, 0.f),
                         fmaxf(acc[mt][nt][1] + bv0, 0.f));
            *(uint2*)&outp[(size_t)pc * HW + orow + col] = u;
        }
    }
}

// ---------------------------------------------------------------------------
// Final gate, per-batch: grid 64 blocks.
// ---------------------------------------------------------------------------
__global__ __launch_bounds__(256)
void k_final4(const unsigned* __restrict__ a2p, const float* __restrict__ a3w,
              const float* __restrict__ a3b, const float* __restrict__ x,
              float* __restrict__ out)
{
    int t   = blockIdx.x * 256 + threadIdx.x;    // [0, 16384)
    int hw  = t * 4;

    const unsigned* ab = a2p + hw;
    float bv = a3b[0];
    float4 s = {bv, bv, bv, bv};
#pragma unroll
    for (int pc = 0; pc < 16; pc++) {
        int c0 = ((pc >> 3) * 16) + (pc & 7);
        float w0 = a3w[c0], w1 = a3w[c0 + 8];
        uint4 u = *(const uint4*)&ab[(size_t)pc * HW];
        float2 v0 = unpackbf(u.x), v1 = unpackbf(u.y);
        float2 v2 = unpackbf(u.z), v3 = unpackbf(u.w);
        s.x = fmaf(w0, v0.x, fmaf(w1, v0.y, s.x));
        s.y = fmaf(w0, v1.x, fmaf(w1, v1.y, s.y));
        s.z = fmaf(w0, v2.x, fmaf(w1, v2.y, s.z));
        s.w = fmaf(w0, v3.x, fmaf(w1, v3.y, s.w));
    }
    float4 g;
    g.x = 1.f / (1.f + expf(-s.x));
    g.y = 1.f / (1.f + expf(-s.y));
    g.z = 1.f / (1.f + expf(-s.z));
    g.w = 1.f / (1.f + expf(-s.w));

    const float* xb = x + hw;
    float*       ob = out + hw;
#pragma unroll 8
    for (int c = 0; c < 64; c++) {
        float4 v = *(const float4*)&xb[(size_t)c * HW];
        float4 r;
        r.x = fmaxf(v.x * g.x, 0.f);
        r.y = fmaxf(v.y * g.y, 0.f);
        r.z = fmaxf(v.z * g.z, 0.f);
        r.w = fmaxf(v.w * g.w, 0.f);
        *(float4*)&ob[(size_t)c * HW] = r;
    }
}

// ---------------------------------------------------------------------------
// Per-batch stream pipeline resources (created once; handles only, no device
// memory). Work per call is identical; streams/events become graph edges
// under capture via the event fork/join below.
// ---------------------------------------------------------------------------
struct Pipes {
    cudaStream_t s[BATCH];
    cudaEvent_t  root;
    cudaEvent_t  join[BATCH];
    Pipes() {
        s[0] = 0;   // default (capture-origin) stream
        for (int i = 1; i < BATCH; i++)
            cudaStreamCreateWithFlags(&s[i], cudaStreamNonBlocking);
        cudaEventCreateWithFlags(&root, cudaEventDisableTiming);
        for (int i = 0; i < BATCH; i++)
            cudaEventCreateWithFlags(&join[i], cudaEventDisableTiming);
    }
};
static Pipes& pipes() { static Pipes p; return p; }

extern "C" void kernel_launch(void* const* d_in, const int* in_sizes, int n_in,
                              void* d_out, int out_size)
{
    const float* x       = (const float*)d_in[0];
    const float* w_in    = (const float*)d_in[1];
    const float* w_up    = (const float*)d_in[2];
    const float* b_up    = (const float*)d_in[3];
    const float* w_right = (const float*)d_in[4];
    const float* b_right = (const float*)d_in[5];
    const float* w_down  = (const float*)d_in[6];
    const float* b_down  = (const float*)d_in[7];
    const float* w_left  = (const float*)d_in[8];
    const float* b_left  = (const float*)d_in[9];
    const float* wD2     = (const float*)d_in[10];
    const float* a1_w    = (const float*)d_in[11];
    const float* a1_b    = (const float*)d_in[12];
    const float* a2_w    = (const float*)d_in[13];
    const float* a2_b    = (const float*)d_in[14];
    const float* a3_w    = (const float*)d_in[15];
    const float* a3_b    = (const float*)d_in[16];
    float* out = (float*)d_out;

    unsigned *p_out1p, *p_catp, *p_out2p, *p_a1p, *p_a2p;
    cudaGetSymbolAddress((void**)&p_out1p, g_out1p);
    cudaGetSymbolAddress((void**)&p_catp,  g_catp);
    cudaGetSymbolAddress((void**)&p_out2p, g_out2p);
    cudaGetSymbolAddress((void**)&p_a1p,   g_a1p);
    cudaGetSymbolAddress((void**)&p_a2p,   g_a2p);

    cudaFuncSetAttribute(k_gemm_tc64,
                         cudaFuncAttributeMaxDynamicSharedMemorySize, G64_SMEM);
    cudaFuncSetAttribute(k_gemm256_bf16,
                         cudaFuncAttributeMaxDynamicSharedMemorySize, G256_SMEM);
    cudaFuncSetAttribute(k_conv3p<32>,
                         cudaFuncAttributeMaxDynamicSharedMemorySize, CONV_SMEM);
    cudaFuncSetAttribute(k_conv3p<16>,
                         cudaFuncAttributeMaxDynamicSharedMemorySize, CONV_SMEM);

    Pipes& P = pipes();

    // fork: streams 1..3 wait on the origin stream
    cudaEventRecord(P.root, P.s[0]);
    for (int i = 1; i < BATCH; i++)
        cudaStreamWaitEvent(P.s[i], P.root, 0);

    for (int b = 0; b < BATCH; b++) {
        cudaStream_t s = P.s[b];
        const float*    xb  = x       + (size_t)b * 64  * HW;
        unsigned*       o1  = p_out1p + (size_t)b * 32  * HW;
        unsigned*       cat = p_catp  + (size_t)b * 128 * HW;
        unsigned*       o2  = p_out2p + (size_t)b * 32  * HW;
        unsigned*       a1  = p_a1p   + (size_t)b * 16  * HW;
        unsigned*       a2  = p_a2p   + (size_t)b * 16  * HW;
        float*          ob  = out     + (size_t)b * 64  * HW;

        // 1) out1p = conv1x1(x, w_in)   (TF32 MMA)
        k_gemm_tc64<<<dim3(256, 1, 1), 256, G64_SMEM, s>>>(w_in, xb, o1);

        // 2) 4-direction scans (128 blocks: 4 dirs x 32 pc)
        k_scans4<<<128, 256, 0, s>>>(o1, cat,
                                     w_up, b_up, w_right, b_right,
                                     w_down, b_down, w_left, b_left);

        // 3) out2p = relu(conv1x1(cat, wD2))   bf16 MMA + cp.async ring
        k_gemm256_bf16<<<dim3(256, 1, 1), 256, G256_SMEM, s>>>(wD2, cat, o2);

        // 4) a1p = relu(conv3x3(out2, a1_w) + a1_b)
        k_conv3p<32><<<dim3(128, 1, 1), 256, CONV_SMEM, s>>>(o2, a1_w, a1_b, a1);

        // 5) a2p = relu(conv3x3(a1, a2_w) + a2_b)
        k_conv3p<16><<<dim3(128, 1, 1), 256, CONV_SMEM, s>>>(a1, a2_w, a2_b, a2);

        // 6) out = relu(x * sigmoid(a3_w . a2 + a3_b))
        k_final4<<<64, 256, 0, s>>>(a2, a3_w, a3_b, xb, ob);
    }

    // join: origin stream waits for streams 1..3
    for (int i = 1; i < BATCH; i++) {
        cudaEventRecord(P.join[i], P.s[i]);
        cudaStreamWaitEvent(P.s[0], P.join[i], 0);
    }
}

// round 17
// speedup vs baseline: 1.0925x; 1.0925x over previous
#include <cuda_runtime.h>
#include <cuda_bf16.h>
#include <math.h>
#include <stdint.h>

#define HW      65536
#define BATCH   4

// ---------------- scratch (device globals; no allocation allowed) ----------
// pair channel pc <-> fp channels (c0, c1): c0 = (pc>>3)*16 + (pc&7), c1 = c0+8
__device__ unsigned g_out1p[(size_t)BATCH * 32  * HW];  //  34 MB
__device__ unsigned g_catp [(size_t)BATCH * 128 * HW];  // 134 MB (k2 = dir*32+pc)
__device__ unsigned g_out2p[(size_t)BATCH * 32  * HW];  //  34 MB
__device__ unsigned g_a1p  [(size_t)BATCH * 16  * HW];  //  17 MB

// ---------------- helpers ---------------------------------------------------
__device__ __forceinline__ unsigned packbf(float hi, float lo) {
    unsigned r;
    asm("cvt.rn.bf16x2.f32 %0, %1, %2;" : "=r"(r) : "f"(hi), "f"(lo));
    return r;
}
__device__ __forceinline__ float2 unpackbf(unsigned u) {
    __nv_bfloat162 h = *reinterpret_cast<__nv_bfloat162*>(&u);
    return __bfloat1622float2(h);
}
__device__ __forceinline__ void cpasync16(void* dst, const void* src) {
    unsigned d = (unsigned)__cvta_generic_to_shared(dst);
    asm volatile("cp.async.cg.shared.global [%0], [%1], 16;" :: "r"(d), "l"(src));
}

#define MMA_BF16(c, a, b0, b1)                                              \
    asm volatile("mma.sync.aligned.m16n8k16.row.col.f32.bf16.bf16.f32 "     \
        "{%0,%1,%2,%3}, {%4,%5,%6,%7}, {%8,%9}, {%0,%1,%2,%3};"             \
        : "+f"((c)[0]), "+f"((c)[1]), "+f"((c)[2]), "+f"((c)[3])            \
        : "r"((a)[0]), "r"((a)[1]), "r"((a)[2]), "r"((a)[3]),               \
          "r"(b0), "r"(b1))

// ---------------------------------------------------------------------------
// BF16 GEMM stage 1 (K=64): out1p(packed) = w_in @ x.
// X staged fp32 via cp.async (stride 260 -> conflict-free 8rt+qt banks),
// B fragments packed to bf16x2 on the fly; A pre-packed bf16 pairs.
// Block M64 x N256, 4 k16 steps. grid (256,1,4).
// ---------------------------------------------------------------------------
#define G64_XS   (64 * 260)             // fp32 words
#define G64_WS   (64 * 36)              // packed bf16x2 words
#define G64_SMEM ((G64_XS + G64_WS) * 4)

__global__ __launch_bounds__(256, 2)
void k_gemm64_bf16(const float* __restrict__ Wt, const float* __restrict__ X,
                   unsigned* __restrict__ Yp)
{
    extern __shared__ float dsm64[];
    float*    xs = dsm64;                          // [64][260] fp32
    unsigned* ws = (unsigned*)(dsm64 + G64_XS);    // [64][36]  bf16x2 k-pairs

    const int tid  = threadIdx.x;
    const int warp = tid >> 5;
    const int lane = tid & 31;
    const int n0   = blockIdx.x * 256;
    const int b    = blockIdx.z;
    const float* Xb = X  + (size_t)b * 64 * HW;
    unsigned*    Yb = Yp + (size_t)b * 32 * HW;

    const int mw = (warp & 1) * 32;
    const int nw = (warp >> 1) * 64;
    const int qt = lane >> 2;
    const int rt = lane & 3;

    // stage whole X tile (64 rows x 256 cols fp32) via cp.async
#pragma unroll
    for (int j = 0; j < 16; j++) {
        int idx = tid + j * 256;
        int k   = idx >> 6;
        int c4  = (idx & 63) * 4;
        cpasync16(&xs[k * 260 + c4], Xb + (size_t)k * HW + n0 + c4);
    }
    asm volatile("cp.async.commit_group;");

    // stage W packed: ws[m][j] = bf16x2(W[m][2j], W[m][2j+1])
#pragma unroll
    for (int i = 0; i < 8; i++) {
        int e = tid + i * 256;
        int m = e >> 5, j = e & 31;
        float2 w2 = *(const float2*)&Wt[m * 64 + 2 * j];
        ws[m * 36 + j] = packbf(w2.y, w2.x);
    }
    asm volatile("cp.async.wait_group 0;");
    __syncthreads();

    float acc[2][8][4];
#pragma unroll
    for (int i = 0; i < 2; i++)
#pragma unroll
        for (int j = 0; j < 8; j++)
#pragma unroll
            for (int v = 0; v < 4; v++) acc[i][j][v] = 0.f;

#pragma unroll
    for (int kk = 0; kk < 4; kk++) {
        const int kb = kk * 8;          // k-pair word base
        unsigned a[2][4];
#pragma unroll
        for (int mt = 0; mt < 2; mt++) {
            int mr = mw + mt * 16 + qt;
            a[mt][0] = ws[mr * 36 + kb + rt];
            a[mt][1] = ws[(mr + 8) * 36 + kb + rt];
            a[mt][2] = ws[mr * 36 + kb + rt + 4];
            a[mt][3] = ws[(mr + 8) * 36 + kb + rt + 4];
        }
#pragma unroll
        for (int nt = 0; nt < 8; nt++) {
            int col = nw + nt * 8 + qt;
            int r0  = 2 * (kb + rt);
            int r1  = 2 * (kb + rt + 4);
            unsigned b0 = packbf(xs[(r0 + 1) * 260 + col], xs[r0 * 260 + col]);
            unsigned b1 = packbf(xs[(r1 + 1) * 260 + col], xs[r1 * 260 + col]);
            MMA_BF16(acc[0][nt], a[0], b0, b1);
            MMA_BF16(acc[1][nt], a[1], b0, b1);
        }
    }

    // epilogue: pack rows (mr, mr+8) -> pair channel pc = (mr>>4)*8 + qt
#pragma unroll
    for (int mt = 0; mt < 2; mt++) {
        int pc = ((mw >> 4) + mt) * 8 + qt;
#pragma unroll
        for (int nt = 0; nt < 8; nt++) {
            int col = n0 + nw + nt * 8 + rt * 2;
            uint2 u;
            u.x = packbf(acc[mt][nt][2], acc[mt][nt][0]);
            u.y = packbf(acc[mt][nt][3], acc[mt][nt][1]);
            *(uint2*)&Yb[(size_t)pc * HW + col] = u;
        }
    }
}

// ---------------------------------------------------------------------------
// 4-direction IRNN scans, one pass per block (fwd/bwd split).
// 512 blocks: [0,128) down, [128,256) up, [256,384) right, [384,512) left.
// ---------------------------------------------------------------------------
__global__ __launch_bounds__(256)
void k_scans4(const unsigned* __restrict__ srcp, unsigned* __restrict__ catp,
              const float* __restrict__ w_up, const float* __restrict__ b_up,
              const float* __restrict__ w_rt, const float* __restrict__ b_rt,
              const float* __restrict__ w_dn, const float* __restrict__ b_dn,
              const float* __restrict__ w_lt, const float* __restrict__ b_lt)
{
    const int dir = blockIdx.x >> 7;
    const int blk = blockIdx.x & 127;
    const int tid = threadIdx.x;
    const int pc  = blk & 31;
    const int b   = blk >> 5;
    const int c0  = ((pc >> 3) * 16) + (pc & 7);
    const int c1  = c0 + 8;

    const float *wv, *bv;
    int k2off; bool vert, fwd;
    if (dir == 0)      { wv = w_dn; bv = b_dn; k2off = 64; vert = true;  fwd = true;  }
    else if (dir == 1) { wv = w_up; bv = b_up; k2off = 0;  vert = true;  fwd = false; }
    else if (dir == 2) { wv = w_rt; bv = b_rt; k2off = 32; vert = false; fwd = true;  }
    else               { wv = w_lt; bv = b_lt; k2off = 96; vert = false; fwd = false; }

    const float W0 = wv[c0], W1 = wv[c1], B0 = bv[c0], B1 = bv[c1];

    int off  = vert ? tid : tid * 256;
    int step = vert ? 256 : 1;
    if (!fwd) { off += step * 255; step = -step; }

    const unsigned* sp = srcp + (((size_t)b * 32 + pc) << 16) + off;
    unsigned*       dp = catp + (((size_t)b * 128 + k2off + pc) << 16) + off;

    float h0 = 0.f, h1 = 0.f;
    unsigned v = *sp;
    sp += step;
#pragma unroll 8
    for (int i = 0; i < 256; i++) {
        unsigned vn = 0;
        if (i < 255) vn = *sp;          // prefetch: independent of the fma chain
        sp += step;
        float2 f = unpackbf(v);
        h0 = fmaxf(fmaf(W0, h0, f.x + B0), 0.f);
        h1 = fmaxf(fmaf(W1, h1, f.y + B1), 0.f);
        *dp = packbf(h1, h0);
        dp += step;
        v = vn;
    }
}

// ---------------------------------------------------------------------------
// BF16 GEMM stage 3: out2p = relu(wD2 @ cat), K=256 (128 pairs).
// Full A resident in smem (stride 132), 3-stage cp.async ring for B
// (stride 264, conflict-free). grid (256,1,4).
// ---------------------------------------------------------------------------
#define G256_WS   (64 * 132)
#define G256_XSLOT (16 * 264)
#define G256_SMEM ((G256_WS + 3 * G256_XSLOT) * 4)

__global__ __launch_bounds__(256)
void k_gemm256_bf16(const float* __restrict__ Wt, const unsigned* __restrict__ Xp,
                    unsigned* __restrict__ Yp)
{
    extern __shared__ unsigned dsm[];
    unsigned* wsf = dsm;
    unsigned* xsp = dsm + G256_WS;

    const int tid  = threadIdx.x;
    const int warp = tid >> 5;
    const int lane = tid & 31;
    const int n0   = blockIdx.x * 256;
    const int b    = blockIdx.z;
    const unsigned* Xb = Xp + (size_t)b * 128 * HW;
    unsigned*       Yb = Yp + (size_t)b * 32 * HW;

    const int nw = warp * 32;
    const int qt = lane >> 2;
    const int rt = lane & 3;

#pragma unroll
    for (int c = 0; c < 2; c++) {
#pragma unroll
        for (int j = 0; j < 4; j++) {
            int idx = tid + j * 256, row = idx >> 6, col4 = (idx & 63) * 4;
            cpasync16(&xsp[c * G256_XSLOT + row * 264 + col4],
                      Xb + (size_t)(c * 16 + row) * HW + n0 + col4);
        }
        asm volatile("cp.async.commit_group;");
    }

#pragma unroll
    for (int i = 0; i < 32; i++) {
        int e = tid + i * 256;
        int m = e >> 7, l2 = e & 127;
        int d2 = l2 >> 5, pcd = l2 & 31;
        int cc = d2 * 64 + ((pcd >> 3) * 16) + (pcd & 7);
        wsf[m * 132 + l2] = packbf(Wt[m * 256 + cc + 8], Wt[m * 256 + cc]);
    }

    float acc[4][4][4];
#pragma unroll
    for (int i = 0; i < 4; i++)
#pragma unroll
        for (int j = 0; j < 4; j++)
#pragma unroll
            for (int v = 0; v < 4; v++) acc[i][j][v] = 0.f;

    for (int kt = 0; kt < 8; kt++) {
        __syncthreads();
        if (kt + 2 < 8) {
            int sl = (kt + 2) % 3;
#pragma unroll
            for (int j = 0; j < 4; j++) {
                int idx = tid + j * 256, row = idx >> 6, col4 = (idx & 63) * 4;
                cpasync16(&xsp[sl * G256_XSLOT + row * 264 + col4],
                          Xb + (size_t)((kt + 2) * 16 + row) * HW + n0 + col4);
            }
            asm volatile("cp.async.commit_group;");
        }
        if (kt < 6)      asm volatile("cp.async.wait_group 2;");
        else if (kt == 6) asm volatile("cp.async.wait_group 1;");
        else              asm volatile("cp.async.wait_group 0;");
        __syncthreads();

        const unsigned* xc = xsp + (kt % 3) * G256_XSLOT;
        const int kg = kt * 16;
#pragma unroll
        for (int s = 0; s < 2; s++) {
            const int kb = s * 8;
            unsigned a[4][4];
#pragma unroll
            for (int mt = 0; mt < 4; mt++) {
                int m = mt * 16 + qt;
                int k2 = kg + kb + rt;
                a[mt][0] = wsf[m * 132 + k2];
                a[mt][1] = wsf[(m + 8) * 132 + k2];
                a[mt][2] = wsf[m * 132 + k2 + 4];
                a[mt][3] = wsf[(m + 8) * 132 + k2 + 4];
            }
#pragma unroll
            for (int nt = 0; nt < 4; nt++) {
                int col = nw + nt * 8 + qt;
                unsigned b0 = xc[(kb + rt) * 264 + col];
                unsigned b1 = xc[(kb + rt + 4) * 264 + col];
#pragma unroll
                for (int mt = 0; mt < 4; mt++)
                    MMA_BF16(acc[mt][nt], a[mt], b0, b1);
            }
        }
    }

#pragma unroll
    for (int mt = 0; mt < 4; mt++) {
        int pc = mt * 8 + qt;
#pragma unroll
        for (int nt = 0; nt < 4; nt++) {
            int col = n0 + nw + nt * 8 + rt * 2;
            uint2 u;
            u.x = packbf(fmaxf(acc[mt][nt][2], 0.f), fmaxf(acc[mt][nt][0], 0.f));
            u.y = packbf(fmaxf(acc[mt][nt][3], 0.f), fmaxf(acc[mt][nt][1], 0.f));
            *(uint2*)&Yb[(size_t)pc * HW + col] = u;
        }
    }
}

// ---------------------------------------------------------------------------
// Shared conv3x3 machinery (packed-pair bf16 implicit GEMM, R11 recipe).
// ---------------------------------------------------------------------------
#define CONV_XSLOT (4 * 8 * 264)
#define CONV_WSLOT (9 * 8 * 40)
#define CONV_SMEM  ((2 * CONV_XSLOT + 2 * CONV_WSLOT) * 4)

#define STAGE_X(CH, XD)                                                       \
    {                                                                         \
        unsigned* xd = (XD);                                                  \
        _Pragma("unroll")                                                     \
        for (int j = 0; j < 8; j++) {                                         \
            int e  = tid + j * 256;                                           \
            int i2 = e >> 8;                                                  \
            int r  = (e >> 6) & 3;                                            \
            int bk = e & 63;                                                  \
            int hh = h0 + r - 1;                                              \
            unsigned* dst = &xd[(r * 8 + i2) * 264 + 4 + bk * 4];             \
            if ((unsigned)hh < 256u)                                          \
                cpasync16(dst, inb + (size_t)((CH) * 8 + i2) * HW + hh * 256 + bk * 4); \
            else                                                              \
                *(uint4*)dst = make_uint4(0, 0, 0, 0);                        \
        }                                                                     \
        asm volatile("cp.async.commit_group;");                               \
    }

#define STAGE_W(CH, WD, CI)                                                   \
    {                                                                         \
        unsigned* wd = (WD);                                                  \
        for (int e = tid; e < 9 * 8 * 32; e += 256) {                         \
            int tap = e >> 8;                                                 \
            int i2  = (e >> 5) & 7;                                           \
            int o   = e & 31;                                                 \
            int pg  = (CH) * 8 + i2;                                          \
            int cc  = ((pg >> 3) * 16) + (pg & 7);                            \
            const float* p = wt + ((size_t)o * (CI) + cc) * 9 + tap;          \
            wd[(tap * 8 + i2) * 40 + o] = packbf(p[72], p[0]);                \
        }                                                                     \
    }

#define LOADFRAG(TAP, S)                                                      \
    {                                                                         \
        const int r_ = (TAP) / 3, c_ = (TAP) % 3;                             \
        const int ri_ = rw + r_;                                              \
        _Pragma("unroll")                                                     \
        for (int mt = 0; mt < 2; mt++) {                                      \
            int o = mt * 16 + qt;                                             \
            af[S][mt][0] = wc[((TAP) * 8 + rt) * 40 + o];                     \
            af[S][mt][1] = wc[((TAP) * 8 + rt) * 40 + o + 8];                 \
            af[S][mt][2] = wc[((TAP) * 8 + rt + 4) * 40 + o];                 \
            af[S][mt][3] = wc[((TAP) * 8 + rt + 4) * 40 + o + 8];             \
        }                                                                     \
        _Pragma("unroll")                                                     \
        for (int nt = 0; nt < 8; nt++) {                                      \
            int col = strip + nt * 8 + qt + c_ + 3;                           \
            bf[S][nt][0] = xc[(ri_ * 8 + rt) * 264 + col];                    \
            bf[S][nt][1] = xc[(ri_ * 8 + rt + 4) * 264 + col];                \
        }                                                                     \
    }

// mainloop body shared by both conv kernels: fills acc[2][8][4]
#define CONV_MAINLOOP(NCH)                                                    \
    STAGE_X(0, xsb + 0);                                                      \
    STAGE_W(0, wsb + 0, CI);                                                  \
    for (int ch = 0; ch < (NCH); ch++) {                                      \
        const int cur = ch & 1, nxt = cur ^ 1;                                \
        __syncthreads();                                                      \
        if (ch + 1 < (NCH)) {                                                 \
            STAGE_X(ch + 1, xsb + nxt * CONV_XSLOT);                          \
            STAGE_W(ch + 1, wsb + nxt * CONV_WSLOT, CI);                      \
            asm volatile("cp.async.wait_group 1;");                           \
        } else {                                                              \
            asm volatile("cp.async.wait_group 0;");                           \
        }                                                                     \
        __syncthreads();                                                      \
        const unsigned* xc = xsb + cur * CONV_XSLOT;                          \
        const unsigned* wc = wsb + cur * CONV_WSLOT;                          \
        unsigned af[2][2][4];                                                 \
        unsigned bf[2][8][2];                                                 \
        LOADFRAG(0, 0);                                                       \
        _Pragma("unroll")                                                     \
        for (int tap = 0; tap < 9; tap++) {                                   \
            const int cb = tap & 1;                                           \
            if (tap < 8) LOADFRAG(tap + 1, cb ^ 1);                           \
            _Pragma("unroll")                                                 \
            for (int nt = 0; nt < 8; nt++) {                                  \
                MMA_BF16(acc[0][nt], af[cb][0], bf[cb][nt][0], bf[cb][nt][1]);\
                MMA_BF16(acc[1][nt], af[cb][1], bf[cb][nt][0], bf[cb][nt][1]);\
            }                                                                 \
        }                                                                     \
    }

// ---------------------------------------------------------------------------
// conv #1: 64 -> 32 ch, packed output. grid (128,1,4).
// ---------------------------------------------------------------------------
__global__ __launch_bounds__(256, 2)
void k_conv3p32(const unsigned* __restrict__ inp, const float* __restrict__ wt,
                const float* __restrict__ bias, unsigned* __restrict__ outp)
{
    constexpr int CI = 64;

    extern __shared__ unsigned dsm[];
    unsigned* xsb = dsm;
    unsigned* wsb = dsm + 2 * CONV_XSLOT;

    const int h0    = blockIdx.x * 2;
    const int b     = blockIdx.z;
    const int tid   = threadIdx.x;
    const int warp  = tid >> 5;
    const int lane  = tid & 31;
    const int rw    = warp >> 2;
    const int strip = (warp & 3) * 64;
    const int qt    = lane >> 2;
    const int rt    = lane & 3;

    const unsigned* inb = inp + (size_t)b * 32 * HW;

    if (tid < 128) {
        int buf = tid >> 6, rem = tid & 63;
        int side = rem >> 5, rr = (rem >> 3) & 3, i2 = rem & 7;
        xsb[buf * CONV_XSLOT + (rr * 8 + i2) * 264 + (side ? 260 : 3)] = 0u;
    }

    float acc[2][8][4];
#pragma unroll
    for (int i = 0; i < 2; i++)
#pragma unroll
        for (int j = 0; j < 8; j++)
#pragma unroll
            for (int v = 0; v < 4; v++) acc[i][j][v] = 0.f;

    CONV_MAINLOOP(4)

    const int orow = (h0 + rw) * 256;
#pragma unroll
    for (int mt = 0; mt < 2; mt++) {
        int o   = mt * 16 + qt;
        int pc  = mt * 8 + qt;
        float bv0 = bias[o];
        float bv1 = bias[o + 8];
#pragma unroll
        for (int nt = 0; nt < 8; nt++) {
            int col = strip + nt * 8 + rt * 2;
            uint2 u;
            u.x = packbf(fmaxf(acc[mt][nt][2] + bv1, 0.f),
                         fmaxf(acc[mt][nt][0] + bv0, 0.f));
            u.y = packbf(fmaxf(acc[mt][nt][3] + bv1, 0.f),
                         fmaxf(acc[mt][nt][1] + bv0, 0.f));
            *(uint2*)&outp[((size_t)(b * 16 + pc)) * HW + orow + col] = u;
        }
    }
}

// ---------------------------------------------------------------------------
// conv #2 FUSED with the final gate: a2 = relu(conv3x3(a1) + bias) stays in
// registers; a = a3w . a2 + a3b via per-thread partials + 3 qt-butterflies;
// out = relu(x * sigmoid(a)). Deletes k_final4 and all a2 traffic.
// grid (128,1,4).
// ---------------------------------------------------------------------------
__global__ __launch_bounds__(256, 2)
void k_conv3f(const unsigned* __restrict__ inp, const float* __restrict__ wt,
              const float* __restrict__ bias,
              const float* __restrict__ a3w, const float* __restrict__ a3b,
              const float* __restrict__ x, float* __restrict__ out)
{
    constexpr int CI = 32;

    extern __shared__ unsigned dsm[];
    unsigned* xsb = dsm;
    unsigned* wsb = dsm + 2 * CONV_XSLOT;

    const int h0    = blockIdx.x * 2;
    const int b     = blockIdx.z;
    const int tid   = threadIdx.x;
    const int warp  = tid >> 5;
    const int lane  = tid & 31;
    const int rw    = warp >> 2;
    const int strip = (warp & 3) * 64;
    const int qt    = lane >> 2;
    const int rt    = lane & 3;

    const unsigned* inb = inp + (size_t)b * 16 * HW;

    if (tid < 128) {
        int buf = tid >> 6, rem = tid & 63;
        int side = rem >> 5, rr = (rem >> 3) & 3, i2 = rem & 7;
        xsb[buf * CONV_XSLOT + (rr * 8 + i2) * 264 + (side ? 260 : 3)] = 0u;
    }

    float acc[2][8][4];
#pragma unroll
    for (int i = 0; i < 2; i++)
#pragma unroll
        for (int j = 0; j < 8; j++)
#pragma unroll
            for (int v = 0; v < 4; v++) acc[i][j][v] = 0.f;

    CONV_MAINLOOP(2)

    // ---- fused epilogue: bias+relu -> a3 dot -> sigmoid -> gate ----
    const int orow  = (h0 + rw) * 256;
    const float a3b0 = a3b[0];
    const float aw0 = a3w[qt],      aw1 = a3w[qt + 8];
    const float aw2 = a3w[qt + 16], aw3 = a3w[qt + 24];
    const float bb0 = bias[qt],      bb1 = bias[qt + 8];
    const float bb2 = bias[qt + 16], bb3 = bias[qt + 24];

    float2 g2[8];
#pragma unroll
    for (int nt = 0; nt < 8; nt++) {
        float dv[2];
#pragma unroll
        for (int cv = 0; cv < 2; cv++) {
            float v0 = fmaxf(acc[0][nt][cv]     + bb0, 0.f);
            float v1 = fmaxf(acc[0][nt][cv + 2] + bb1, 0.f);
            float v2 = fmaxf(acc[1][nt][cv]     + bb2, 0.f);
            float v3 = fmaxf(acc[1][nt][cv + 2] + bb3, 0.f);
            float d = fmaf(aw0, v0, fmaf(aw1, v1, fmaf(aw2, v2, aw3 * v3)));
            d += __shfl_xor_sync(0xffffffffu, d, 4);
            d += __shfl_xor_sync(0xffffffffu, d, 8);
            d += __shfl_xor_sync(0xffffffffu, d, 16);
            dv[cv] = 1.f / (1.f + expf(-(d + a3b0)));
        }
        g2[nt].x = dv[0];
        g2[nt].y = dv[1];
    }

    // gate: thread handles channels qt*8..qt*8+7 over its 8 col-pairs
    const float* xb = x   + ((size_t)(b * 64 + qt * 8)) * HW + orow;
    float*       ob = out + ((size_t)(b * 64 + qt * 8)) * HW + orow;
#pragma unroll
    for (int c = 0; c < 8; c++) {
#pragma unroll
        for (int nt = 0; nt < 8; nt++) {
            int col = strip + nt * 8 + rt * 2;
            float2 xv = *(const float2*)&xb[(size_t)c * HW + col];
            float2 r;
            r.x = fmaxf(xv.x * g2[nt].x, 0.f);
            r.y = fmaxf(xv.y * g2[nt].y, 0.f);
            *(float2*)&ob[(size_t)c * HW + col] = r;
        }
    }
}

// ---------------------------------------------------------------------------
extern "C" void kernel_launch(void* const* d_in, const int* in_sizes, int n_in,
                              void* d_out, int out_size)
{
    const float* x       = (const float*)d_in[0];
    const float* w_in    = (const float*)d_in[1];
    const float* w_up    = (const float*)d_in[2];
    const float* b_up    = (const float*)d_in[3];
    const float* w_right = (const float*)d_in[4];
    const float* b_right = (const float*)d_in[5];
    const float* w_down  = (const float*)d_in[6];
    const float* b_down  = (const float*)d_in[7];
    const float* w_left  = (const float*)d_in[8];
    const float* b_left  = (const float*)d_in[9];
    const float* wD2     = (const float*)d_in[10];
    const float* a1_w    = (const float*)d_in[11];
    const float* a1_b    = (const float*)d_in[12];
    const float* a2_w    = (const float*)d_in[13];
    const float* a2_b    = (const float*)d_in[14];
    const float* a3_w    = (const float*)d_in[15];
    const float* a3_b    = (const float*)d_in[16];
    float* out = (float*)d_out;

    unsigned *p_out1p, *p_catp, *p_out2p, *p_a1p;
    cudaGetSymbolAddress((void**)&p_out1p, g_out1p);
    cudaGetSymbolAddress((void**)&p_catp,  g_catp);
    cudaGetSymbolAddress((void**)&p_out2p, g_out2p);
    cudaGetSymbolAddress((void**)&p_a1p,   g_a1p);

    cudaFuncSetAttribute(k_gemm64_bf16,
                         cudaFuncAttributeMaxDynamicSharedMemorySize, G64_SMEM);
    cudaFuncSetAttribute(k_gemm256_bf16,
                         cudaFuncAttributeMaxDynamicSharedMemorySize, G256_SMEM);
    cudaFuncSetAttribute(k_conv3p32,
                         cudaFuncAttributeMaxDynamicSharedMemorySize, CONV_SMEM);
    cudaFuncSetAttribute(k_conv3f,
                         cudaFuncAttributeMaxDynamicSharedMemorySize, CONV_SMEM);

    dim3 gGemm(HW / 256, 1, BATCH);      // (256,1,4)
    dim3 gConv(128, 1, BATCH);

    // 1) out1p = conv1x1(x, w_in)   (bf16 MMA, cp.async staging)
    k_gemm64_bf16<<<gGemm, 256, G64_SMEM>>>(w_in, x, p_out1p);

    // 2) 4-direction scans, fwd/bwd split (512 independent blocks)
    k_scans4<<<512, 256>>>(p_out1p, p_catp,
                           w_up, b_up, w_right, b_right,
                           w_down, b_down, w_left, b_left);

    // 3) out2p = relu(conv1x1(cat, wD2))   bf16 MMA, 3-stage cp.async ring
    k_gemm256_bf16<<<gGemm, 256, G256_SMEM>>>(wD2, p_catp, p_out2p);

    // 4) a1p = relu(conv3x3(out2, a1_w) + a1_b)
    k_conv3p32<<<gConv, 256, CONV_SMEM>>>(p_out2p, a1_w, a1_b, p_a1p);

    // 5+6) fused: a2 = relu(conv3x3(a1)+b); out = relu(x * sigmoid(a3.a2+a3b))
    k_conv3f<<<gConv, 256, CONV_SMEM>>>(p_a1p, a2_w, a2_b,
                                        a3_w, a3_b, x, out);
}